// round 1
// baseline (speedup 1.0000x reference)
#include <cuda_runtime.h>
#include <math.h>

#define BB 4
#define SS 1024
#define DD 1024
#define HH 16
#define DKK 64
#define DFFV 4096
#define MR (BB*SS)   // 4096 rows
#define LN_EPS 1e-6f

// ---------------- scratch (device globals; no allocation) ----------------
__device__ float g_xn [MR*DD];
__device__ float g_q  [MR*DD];
__device__ float g_k  [MR*DD];
__device__ float g_v  [MR*DD];
__device__ float g_ctx[MR*DD];
__device__ float g_x1 [MR*DD];
__device__ float g_xn2[MR*DD];
__device__ float g_ffh[MR*DFFV];

// ---------------- LayerNorm (torch ddof=1, eps on std) ----------------
__global__ __launch_bounds__(256)
void layernorm_kernel(const float* __restrict__ x, float* __restrict__ out,
                      const float* __restrict__ alpha, const float* __restrict__ beta)
{
    int row = blockIdx.x;
    const float4* xr = (const float4*)(x + (long)row * DD);
    float4 v = xr[threadIdx.x];                 // 256 thr * 4 = 1024
    float s  = v.x + v.y + v.z + v.w;
    float sq = v.x*v.x + v.y*v.y + v.z*v.z + v.w*v.w;

    #pragma unroll
    for (int o = 16; o; o >>= 1) {
        s  += __shfl_down_sync(0xffffffffu, s,  o);
        sq += __shfl_down_sync(0xffffffffu, sq, o);
    }
    __shared__ float red[16];
    __shared__ float stats[2];
    int warp = threadIdx.x >> 5, lane = threadIdx.x & 31;
    if (lane == 0) { red[warp] = s; red[warp + 8] = sq; }
    __syncthreads();
    if (threadIdx.x == 0) {
        float ts = 0.f, tq = 0.f;
        #pragma unroll
        for (int i = 0; i < 8; i++) { ts += red[i]; tq += red[i + 8]; }
        float mean = ts / (float)DD;
        float var  = (tq - (float)DD * mean * mean) / (float)(DD - 1);
        var = fmaxf(var, 0.f);
        float rstd = 1.f / (sqrtf(var) + LN_EPS);
        stats[0] = mean; stats[1] = rstd;
    }
    __syncthreads();
    float mean = stats[0], rstd = stats[1];
    float a = alpha[0], b = beta[0];
    float4 o;
    o.x = a * (v.x - mean) * rstd + b;
    o.y = a * (v.y - mean) * rstd + b;
    o.z = a * (v.z - mean) * rstd + b;
    o.w = a * (v.w - mean) * rstd + b;
    ((float4*)(out + (long)row * DD))[threadIdx.x] = o;
}

// ---------------- tiled SGEMM: C[M,N] = A[M,K] @ B[K,N] (+bias, relu, res) ----
// BM=BN=128, BK=16, 256 threads, 8x8 per thread in split 4+4 layout.
template<bool BIAS, bool RELU, bool RES>
__global__ __launch_bounds__(256)
void sgemm_kernel(const float* __restrict__ A, const float* __restrict__ Bm,
                  const float* __restrict__ bias, const float* __restrict__ res,
                  float* __restrict__ C, int K, int N)
{
    __shared__ float As[16][128];
    __shared__ float Bs[16][128];

    int tid = threadIdx.x;
    int tx = tid & 15;          // 0..15 -> col groups
    int ty = tid >> 4;          // 0..15 -> row groups
    int rowBase = blockIdx.y * 128;
    int colBase = blockIdx.x * 128;

    const float* Aptr = A + (long)rowBase * K;
    const float* Bptr = Bm + colBase;

    float acc[8][8];
    #pragma unroll
    for (int i = 0; i < 8; i++)
        #pragma unroll
        for (int j = 0; j < 8; j++) acc[i][j] = 0.f;

    for (int k0 = 0; k0 < K; k0 += 16) {
        // load A tile (transposed into smem): 512 float4, 2 per thread
        #pragma unroll
        for (int i = 0; i < 2; i++) {
            int fi = tid + i * 256;
            int r  = fi >> 2;
            int kc = (fi & 3) << 2;
            float4 va = *(const float4*)(Aptr + (long)r * K + k0 + kc);
            As[kc + 0][r] = va.x; As[kc + 1][r] = va.y;
            As[kc + 2][r] = va.z; As[kc + 3][r] = va.w;
        }
        // load B tile: rows k0..k0+15, 128 cols
        #pragma unroll
        for (int i = 0; i < 2; i++) {
            int fi = tid + i * 256;
            int r  = fi >> 5;
            int c  = (fi & 31) << 2;
            *(float4*)(&Bs[r][c]) = *(const float4*)(Bptr + (long)(k0 + r) * N + c);
        }
        __syncthreads();

        #pragma unroll
        for (int kk = 0; kk < 16; kk++) {
            float a[8], b[8];
            float4 a0 = *(const float4*)(&As[kk][ty * 4]);
            float4 a1 = *(const float4*)(&As[kk][64 + ty * 4]);
            float4 b0 = *(const float4*)(&Bs[kk][tx * 4]);
            float4 b1 = *(const float4*)(&Bs[kk][64 + tx * 4]);
            a[0]=a0.x; a[1]=a0.y; a[2]=a0.z; a[3]=a0.w;
            a[4]=a1.x; a[5]=a1.y; a[6]=a1.z; a[7]=a1.w;
            b[0]=b0.x; b[1]=b0.y; b[2]=b0.z; b[3]=b0.w;
            b[4]=b1.x; b[5]=b1.y; b[6]=b1.z; b[7]=b1.w;
            #pragma unroll
            for (int i = 0; i < 8; i++)
                #pragma unroll
                for (int j = 0; j < 8; j++)
                    acc[i][j] += a[i] * b[j];
        }
        __syncthreads();
    }

    // epilogue
    #pragma unroll
    for (int i = 0; i < 8; i++) {
        int row = rowBase + ((i < 4) ? (ty * 4 + i) : (64 + ty * 4 + i - 4));
        #pragma unroll
        for (int jc = 0; jc < 2; jc++) {
            int col = colBase + ((jc == 0) ? (tx * 4) : (64 + tx * 4));
            float4 o;
            o.x = acc[i][jc * 4 + 0];
            o.y = acc[i][jc * 4 + 1];
            o.z = acc[i][jc * 4 + 2];
            o.w = acc[i][jc * 4 + 3];
            if (BIAS) {
                const float4 bb4 = *(const float4*)(bias + col);
                o.x += bb4.x; o.y += bb4.y; o.z += bb4.z; o.w += bb4.w;
            }
            if (RELU) {
                o.x = fmaxf(o.x, 0.f); o.y = fmaxf(o.y, 0.f);
                o.z = fmaxf(o.z, 0.f); o.w = fmaxf(o.w, 0.f);
            }
            if (RES) {
                const float4 r4 = *(const float4*)(res + (long)row * N + col);
                o.x += r4.x; o.y += r4.y; o.z += r4.z; o.w += r4.w;
            }
            *(float4*)(C + (long)row * N + col) = o;
        }
    }
}

// ---------------- flash attention: 64 q-rows per CTA, stream over k-tiles ----
__global__ __launch_bounds__(256)
void attention_kernel(const float* __restrict__ q, const float* __restrict__ k,
                      const float* __restrict__ v, const int* __restrict__ mask,
                      float* __restrict__ ctx)
{
    __shared__ float Qt[64][64];   // Q^T: [k][r]
    __shared__ float KP[64][64];   // K^T: [k][c], later P^T: [j][r]
    __shared__ float Vs[64][64];   // V:   [j][d]

    int bh = blockIdx.y;
    int b = bh / HH, h = bh % HH;
    int q0 = blockIdx.x * 64;
    int tid = threadIdx.x;
    int r = tid >> 2;          // q row within tile (0..63)
    int quad = tid & 3;        // 0..3 -> 16-col slice

    const float* qbase = q + ((long)(b * SS + q0)) * DD + h * DKK;
    const float* kbase = k + ((long)(b * SS)) * DD + h * DKK;
    const float* vbase = v + ((long)(b * SS)) * DD + h * DKK;
    const int* mrow = mask + b * SS;

    // load Q tile transposed
    #pragma unroll
    for (int i = 0; i < 4; i++) {
        int fi = tid + i * 256;          // 0..1023
        int rr = fi >> 4;                // row in tile
        int c4 = (fi & 15) << 2;         // k offset
        float4 va = *(const float4*)(qbase + (long)rr * DD + c4);
        Qt[c4 + 0][rr] = va.x; Qt[c4 + 1][rr] = va.y;
        Qt[c4 + 2][rr] = va.z; Qt[c4 + 3][rr] = va.w;
    }

    float m = -INFINITY, l = 0.f;
    float acc[16];
    #pragma unroll
    for (int d = 0; d < 16; d++) acc[d] = 0.f;

    for (int kt = 0; kt < 16; kt++) {
        int k0 = kt * 64;
        __syncthreads();   // prior KP/Vs consumers done (also orders Qt on iter 0)
        // load K^T and V
        #pragma unroll
        for (int i = 0; i < 4; i++) {
            int fi = tid + i * 256;
            int rr = fi >> 4;
            int c4 = (fi & 15) << 2;
            float4 va = *(const float4*)(kbase + (long)(k0 + rr) * DD + c4);
            KP[c4 + 0][rr] = va.x; KP[c4 + 1][rr] = va.y;
            KP[c4 + 2][rr] = va.z; KP[c4 + 3][rr] = va.w;
            float4 vv = *(const float4*)(vbase + (long)(k0 + rr) * DD + c4);
            *(float4*)(&Vs[rr][c4]) = vv;
        }
        __syncthreads();

        // scores: s[j] = Q[r,:] . K[c,:],  c = quad*16+j
        float s[16];
        #pragma unroll
        for (int j = 0; j < 16; j++) s[j] = 0.f;
        #pragma unroll 8
        for (int kk = 0; kk < 64; kk++) {
            float qv = Qt[kk][r];
            float4 b0 = *(const float4*)(&KP[kk][quad * 16 + 0]);
            float4 b1 = *(const float4*)(&KP[kk][quad * 16 + 4]);
            float4 b2 = *(const float4*)(&KP[kk][quad * 16 + 8]);
            float4 b3 = *(const float4*)(&KP[kk][quad * 16 + 12]);
            s[0]  += qv * b0.x; s[1]  += qv * b0.y; s[2]  += qv * b0.z; s[3]  += qv * b0.w;
            s[4]  += qv * b1.x; s[5]  += qv * b1.y; s[6]  += qv * b1.z; s[7]  += qv * b1.w;
            s[8]  += qv * b2.x; s[9]  += qv * b2.y; s[10] += qv * b2.z; s[11] += qv * b2.w;
            s[12] += qv * b3.x; s[13] += qv * b3.y; s[14] += qv * b3.z; s[15] += qv * b3.w;
        }
        // scale + mask
        float tmax = -INFINITY;
        #pragma unroll
        for (int j = 0; j < 16; j++) {
            s[j] *= 0.125f;                              // 1/sqrt(64)
            if (mrow[k0 + quad * 16 + j] == 0) s[j] = -1e9f;
            tmax = fmaxf(tmax, s[j]);
        }
        tmax = fmaxf(tmax, __shfl_xor_sync(0xffffffffu, tmax, 1));
        tmax = fmaxf(tmax, __shfl_xor_sync(0xffffffffu, tmax, 2));
        float mnew = fmaxf(m, tmax);
        float corr = __expf(m - mnew);                   // 0 on first tile
        float psum = 0.f;
        #pragma unroll
        for (int j = 0; j < 16; j++) {
            float p = __expf(s[j] - mnew);
            s[j] = p;
            psum += p;
        }
        psum += __shfl_xor_sync(0xffffffffu, psum, 1);
        psum += __shfl_xor_sync(0xffffffffu, psum, 2);
        l = l * corr + psum;
        m = mnew;
        #pragma unroll
        for (int d = 0; d < 16; d++) acc[d] *= corr;

        __syncthreads();   // all done reading K^T
        // write P^T into KP
        #pragma unroll
        for (int j = 0; j < 16; j++) KP[quad * 16 + j][r] = s[j];
        __syncthreads();

        // acc += P[r,:] @ V
        #pragma unroll 8
        for (int j = 0; j < 64; j++) {
            float p = KP[j][r];
            float4 v0 = *(const float4*)(&Vs[j][quad * 16 + 0]);
            float4 v1 = *(const float4*)(&Vs[j][quad * 16 + 4]);
            float4 v2 = *(const float4*)(&Vs[j][quad * 16 + 8]);
            float4 v3 = *(const float4*)(&Vs[j][quad * 16 + 12]);
            acc[0]  += p * v0.x; acc[1]  += p * v0.y; acc[2]  += p * v0.z; acc[3]  += p * v0.w;
            acc[4]  += p * v1.x; acc[5]  += p * v1.y; acc[6]  += p * v1.z; acc[7]  += p * v1.w;
            acc[8]  += p * v2.x; acc[9]  += p * v2.y; acc[10] += p * v2.z; acc[11] += p * v2.w;
            acc[12] += p * v3.x; acc[13] += p * v3.y; acc[14] += p * v3.z; acc[15] += p * v3.w;
        }
    }

    float invl = 1.f / l;
    float* obase = ctx + ((long)(b * SS + q0 + r)) * DD + h * DKK + quad * 16;
    #pragma unroll
    for (int d = 0; d < 16; d += 4) {
        float4 o;
        o.x = acc[d + 0] * invl; o.y = acc[d + 1] * invl;
        o.z = acc[d + 2] * invl; o.w = acc[d + 3] * invl;
        *(float4*)(obase + d) = o;
    }
}

// ---------------- launch ----------------
extern "C" void kernel_launch(void* const* d_in, const int* in_sizes, int n_in,
                              void* d_out, int out_size)
{
    const float* x    = (const float*)d_in[0];
    const int*   mask = (const int*)  d_in[1];
    const float* wq = (const float*)d_in[2];  const float* bq = (const float*)d_in[3];
    const float* wk = (const float*)d_in[4];  const float* bk = (const float*)d_in[5];
    const float* wv = (const float*)d_in[6];  const float* bv = (const float*)d_in[7];
    const float* wo = (const float*)d_in[8];  const float* bo = (const float*)d_in[9];
    const float* w1 = (const float*)d_in[10]; const float* b1 = (const float*)d_in[11];
    const float* w2 = (const float*)d_in[12]; const float* b2 = (const float*)d_in[13];
    const float* a1 = (const float*)d_in[14]; const float* be1 = (const float*)d_in[15];
    const float* a2 = (const float*)d_in[16]; const float* be2 = (const float*)d_in[17];
    float* out = (float*)d_out;

    float *xn, *q, *k, *v, *ctx, *x1, *xn2, *ffh;
    cudaGetSymbolAddress((void**)&xn,  g_xn);
    cudaGetSymbolAddress((void**)&q,   g_q);
    cudaGetSymbolAddress((void**)&k,   g_k);
    cudaGetSymbolAddress((void**)&v,   g_v);
    cudaGetSymbolAddress((void**)&ctx, g_ctx);
    cudaGetSymbolAddress((void**)&x1,  g_x1);
    cudaGetSymbolAddress((void**)&xn2, g_xn2);
    cudaGetSymbolAddress((void**)&ffh, g_ffh);

    dim3 gD (DD   / 128, MR / 128);   // (8, 32)
    dim3 gFF(DFFV / 128, MR / 128);   // (32, 32)

    // LN1
    layernorm_kernel<<<MR, 256>>>(x, xn, a1, be1);
    // Q, K, V projections
    sgemm_kernel<true,  false, false><<<gD, 256>>>(xn, wq, bq, nullptr, q, DD, DD);
    sgemm_kernel<true,  false, false><<<gD, 256>>>(xn, wk, bk, nullptr, k, DD, DD);
    sgemm_kernel<true,  false, false><<<gD, 256>>>(xn, wv, bv, nullptr, v, DD, DD);
    // attention
    attention_kernel<<<dim3(SS / 64, BB * HH), 256>>>(q, k, v, mask, ctx);
    // O projection + residual 1
    sgemm_kernel<true,  false, true ><<<gD, 256>>>(ctx, wo, bo, x, x1, DD, DD);
    // LN2
    layernorm_kernel<<<MR, 256>>>(x1, xn2, a2, be2);
    // FFN
    sgemm_kernel<true,  true,  false><<<gFF, 256>>>(xn2, w1, b1, nullptr, ffh, DD, DFFV);
    sgemm_kernel<true,  false, true ><<<gD, 256>>>(ffh, w2, b2, x1, out, DFFV, DD);
}

// round 2
// speedup vs baseline: 1.0003x; 1.0003x over previous
#include <cuda_runtime.h>
#include <math.h>

#define BB 4
#define SS 1024
#define DD 1024
#define HH 16
#define DKK 64
#define DFFV 4096
#define MR (BB*SS)   // 4096 rows
#define LN_EPS 1e-6f

// ---------------- scratch (device globals; no allocation) ----------------
__device__ float g_xn [MR*DD];
__device__ float g_q  [MR*DD];
__device__ float g_k  [MR*DD];
__device__ float g_v  [MR*DD];
__device__ float g_ctx[MR*DD];
__device__ float g_x1 [MR*DD];
__device__ float g_xn2[MR*DD];
__device__ float g_ffh[MR*DFFV];

// ---------------- LayerNorm (torch ddof=1, eps on std) ----------------
__global__ __launch_bounds__(256)
void layernorm_kernel(const float* __restrict__ x, float* __restrict__ out,
                      const float* __restrict__ alpha, const float* __restrict__ beta)
{
    int row = blockIdx.x;
    const float4* xr = (const float4*)(x + (long)row * DD);
    float4 v = xr[threadIdx.x];                 // 256 thr * 4 = 1024
    float s  = v.x + v.y + v.z + v.w;
    float sq = v.x*v.x + v.y*v.y + v.z*v.z + v.w*v.w;

    #pragma unroll
    for (int o = 16; o; o >>= 1) {
        s  += __shfl_down_sync(0xffffffffu, s,  o);
        sq += __shfl_down_sync(0xffffffffu, sq, o);
    }
    __shared__ float red[16];
    __shared__ float stats[2];
    int warp = threadIdx.x >> 5, lane = threadIdx.x & 31;
    if (lane == 0) { red[warp] = s; red[warp + 8] = sq; }
    __syncthreads();
    if (threadIdx.x == 0) {
        float ts = 0.f, tq = 0.f;
        #pragma unroll
        for (int i = 0; i < 8; i++) { ts += red[i]; tq += red[i + 8]; }
        float mean = ts / (float)DD;
        float var  = (tq - (float)DD * mean * mean) / (float)(DD - 1);
        var = fmaxf(var, 0.f);
        float rstd = 1.f / (sqrtf(var) + LN_EPS);
        stats[0] = mean; stats[1] = rstd;
    }
    __syncthreads();
    float mean = stats[0], rstd = stats[1];
    float a = alpha[0], b = beta[0];
    float4 o;
    o.x = a * (v.x - mean) * rstd + b;
    o.y = a * (v.y - mean) * rstd + b;
    o.z = a * (v.z - mean) * rstd + b;
    o.w = a * (v.w - mean) * rstd + b;
    ((float4*)(out + (long)row * DD))[threadIdx.x] = o;
}

// ---------------- tiled SGEMM: C[M,N] = A[M,K] @ B[K,N] (+bias, relu, res) ----
// BM=BN=128, BK=16, 256 threads, 8x8 per thread in split 4+4 layout.
template<bool BIAS, bool RELU, bool RES>
__global__ __launch_bounds__(256)
void sgemm_kernel(const float* __restrict__ A, const float* __restrict__ Bm,
                  const float* __restrict__ bias, const float* __restrict__ res,
                  float* __restrict__ C, int K, int N)
{
    __shared__ float As[16][128];
    __shared__ float Bs[16][128];

    int tid = threadIdx.x;
    int tx = tid & 15;          // 0..15 -> col groups
    int ty = tid >> 4;          // 0..15 -> row groups
    int rowBase = blockIdx.y * 128;
    int colBase = blockIdx.x * 128;

    const float* Aptr = A + (long)rowBase * K;
    const float* Bptr = Bm + colBase;

    float acc[8][8];
    #pragma unroll
    for (int i = 0; i < 8; i++)
        #pragma unroll
        for (int j = 0; j < 8; j++) acc[i][j] = 0.f;

    for (int k0 = 0; k0 < K; k0 += 16) {
        // load A tile (transposed into smem): 512 float4, 2 per thread
        #pragma unroll
        for (int i = 0; i < 2; i++) {
            int fi = tid + i * 256;
            int r  = fi >> 2;
            int kc = (fi & 3) << 2;
            float4 va = *(const float4*)(Aptr + (long)r * K + k0 + kc);
            As[kc + 0][r] = va.x; As[kc + 1][r] = va.y;
            As[kc + 2][r] = va.z; As[kc + 3][r] = va.w;
        }
        // load B tile: rows k0..k0+15, 128 cols
        #pragma unroll
        for (int i = 0; i < 2; i++) {
            int fi = tid + i * 256;
            int r  = fi >> 5;
            int c  = (fi & 31) << 2;
            *(float4*)(&Bs[r][c]) = *(const float4*)(Bptr + (long)(k0 + r) * N + c);
        }
        __syncthreads();

        #pragma unroll
        for (int kk = 0; kk < 16; kk++) {
            float a[8], b[8];
            float4 a0 = *(const float4*)(&As[kk][ty * 4]);
            float4 a1 = *(const float4*)(&As[kk][64 + ty * 4]);
            float4 b0 = *(const float4*)(&Bs[kk][tx * 4]);
            float4 b1 = *(const float4*)(&Bs[kk][64 + tx * 4]);
            a[0]=a0.x; a[1]=a0.y; a[2]=a0.z; a[3]=a0.w;
            a[4]=a1.x; a[5]=a1.y; a[6]=a1.z; a[7]=a1.w;
            b[0]=b0.x; b[1]=b0.y; b[2]=b0.z; b[3]=b0.w;
            b[4]=b1.x; b[5]=b1.y; b[6]=b1.z; b[7]=b1.w;
            #pragma unroll
            for (int i = 0; i < 8; i++)
                #pragma unroll
                for (int j = 0; j < 8; j++)
                    acc[i][j] += a[i] * b[j];
        }
        __syncthreads();
    }

    // epilogue
    #pragma unroll
    for (int i = 0; i < 8; i++) {
        int row = rowBase + ((i < 4) ? (ty * 4 + i) : (64 + ty * 4 + i - 4));
        #pragma unroll
        for (int jc = 0; jc < 2; jc++) {
            int col = colBase + ((jc == 0) ? (tx * 4) : (64 + tx * 4));
            float4 o;
            o.x = acc[i][jc * 4 + 0];
            o.y = acc[i][jc * 4 + 1];
            o.z = acc[i][jc * 4 + 2];
            o.w = acc[i][jc * 4 + 3];
            if (BIAS) {
                const float4 bb4 = *(const float4*)(bias + col);
                o.x += bb4.x; o.y += bb4.y; o.z += bb4.z; o.w += bb4.w;
            }
            if (RELU) {
                o.x = fmaxf(o.x, 0.f); o.y = fmaxf(o.y, 0.f);
                o.z = fmaxf(o.z, 0.f); o.w = fmaxf(o.w, 0.f);
            }
            if (RES) {
                const float4 r4 = *(const float4*)(res + (long)row * N + col);
                o.x += r4.x; o.y += r4.y; o.z += r4.z; o.w += r4.w;
            }
            *(float4*)(C + (long)row * N + col) = o;
        }
    }
}

// ---------------- flash attention: 64 q-rows per CTA, stream over k-tiles ----
__global__ __launch_bounds__(256)
void attention_kernel(const float* __restrict__ q, const float* __restrict__ k,
                      const float* __restrict__ v, const int* __restrict__ mask,
                      float* __restrict__ ctx)
{
    __shared__ float Qt[64][64];   // Q^T: [k][r]
    __shared__ float KP[64][64];   // K^T: [k][c], later P^T: [j][r]
    __shared__ float Vs[64][64];   // V:   [j][d]

    int bh = blockIdx.y;
    int b = bh / HH, h = bh % HH;
    int q0 = blockIdx.x * 64;
    int tid = threadIdx.x;
    int r = tid >> 2;          // q row within tile (0..63)
    int quad = tid & 3;        // 0..3 -> 16-col slice

    const float* qbase = q + ((long)(b * SS + q0)) * DD + h * DKK;
    const float* kbase = k + ((long)(b * SS)) * DD + h * DKK;
    const float* vbase = v + ((long)(b * SS)) * DD + h * DKK;
    const int* mrow = mask + b * SS;

    // load Q tile transposed
    #pragma unroll
    for (int i = 0; i < 4; i++) {
        int fi = tid + i * 256;          // 0..1023
        int rr = fi >> 4;                // row in tile
        int c4 = (fi & 15) << 2;         // k offset
        float4 va = *(const float4*)(qbase + (long)rr * DD + c4);
        Qt[c4 + 0][rr] = va.x; Qt[c4 + 1][rr] = va.y;
        Qt[c4 + 2][rr] = va.z; Qt[c4 + 3][rr] = va.w;
    }

    float m = -INFINITY, l = 0.f;
    float acc[16];
    #pragma unroll
    for (int d = 0; d < 16; d++) acc[d] = 0.f;

    for (int kt = 0; kt < 16; kt++) {
        int k0 = kt * 64;
        __syncthreads();   // prior KP/Vs consumers done (also orders Qt on iter 0)
        // load K^T and V
        #pragma unroll
        for (int i = 0; i < 4; i++) {
            int fi = tid + i * 256;
            int rr = fi >> 4;
            int c4 = (fi & 15) << 2;
            float4 va = *(const float4*)(kbase + (long)(k0 + rr) * DD + c4);
            KP[c4 + 0][rr] = va.x; KP[c4 + 1][rr] = va.y;
            KP[c4 + 2][rr] = va.z; KP[c4 + 3][rr] = va.w;
            float4 vv = *(const float4*)(vbase + (long)(k0 + rr) * DD + c4);
            *(float4*)(&Vs[rr][c4]) = vv;
        }
        __syncthreads();

        // scores: s[j] = Q[r,:] . K[c,:],  c = quad*16+j
        float s[16];
        #pragma unroll
        for (int j = 0; j < 16; j++) s[j] = 0.f;
        #pragma unroll 8
        for (int kk = 0; kk < 64; kk++) {
            float qv = Qt[kk][r];
            float4 b0 = *(const float4*)(&KP[kk][quad * 16 + 0]);
            float4 b1 = *(const float4*)(&KP[kk][quad * 16 + 4]);
            float4 b2 = *(const float4*)(&KP[kk][quad * 16 + 8]);
            float4 b3 = *(const float4*)(&KP[kk][quad * 16 + 12]);
            s[0]  += qv * b0.x; s[1]  += qv * b0.y; s[2]  += qv * b0.z; s[3]  += qv * b0.w;
            s[4]  += qv * b1.x; s[5]  += qv * b1.y; s[6]  += qv * b1.z; s[7]  += qv * b1.w;
            s[8]  += qv * b2.x; s[9]  += qv * b2.y; s[10] += qv * b2.z; s[11] += qv * b2.w;
            s[12] += qv * b3.x; s[13] += qv * b3.y; s[14] += qv * b3.z; s[15] += qv * b3.w;
        }
        // scale + mask
        float tmax = -INFINITY;
        #pragma unroll
        for (int j = 0; j < 16; j++) {
            s[j] *= 0.125f;                              // 1/sqrt(64)
            if (mrow[k0 + quad * 16 + j] == 0) s[j] = -1e9f;
            tmax = fmaxf(tmax, s[j]);
        }
        tmax = fmaxf(tmax, __shfl_xor_sync(0xffffffffu, tmax, 1));
        tmax = fmaxf(tmax, __shfl_xor_sync(0xffffffffu, tmax, 2));
        float mnew = fmaxf(m, tmax);
        float corr = __expf(m - mnew);                   // 0 on first tile
        float psum = 0.f;
        #pragma unroll
        for (int j = 0; j < 16; j++) {
            float p = __expf(s[j] - mnew);
            s[j] = p;
            psum += p;
        }
        psum += __shfl_xor_sync(0xffffffffu, psum, 1);
        psum += __shfl_xor_sync(0xffffffffu, psum, 2);
        l = l * corr + psum;
        m = mnew;
        #pragma unroll
        for (int d = 0; d < 16; d++) acc[d] *= corr;

        __syncthreads();   // all done reading K^T
        // write P^T into KP
        #pragma unroll
        for (int j = 0; j < 16; j++) KP[quad * 16 + j][r] = s[j];
        __syncthreads();

        // acc += P[r,:] @ V
        #pragma unroll 8
        for (int j = 0; j < 64; j++) {
            float p = KP[j][r];
            float4 v0 = *(const float4*)(&Vs[j][quad * 16 + 0]);
            float4 v1 = *(const float4*)(&Vs[j][quad * 16 + 4]);
            float4 v2 = *(const float4*)(&Vs[j][quad * 16 + 8]);
            float4 v3 = *(const float4*)(&Vs[j][quad * 16 + 12]);
            acc[0]  += p * v0.x; acc[1]  += p * v0.y; acc[2]  += p * v0.z; acc[3]  += p * v0.w;
            acc[4]  += p * v1.x; acc[5]  += p * v1.y; acc[6]  += p * v1.z; acc[7]  += p * v1.w;
            acc[8]  += p * v2.x; acc[9]  += p * v2.y; acc[10] += p * v2.z; acc[11] += p * v2.w;
            acc[12] += p * v3.x; acc[13] += p * v3.y; acc[14] += p * v3.z; acc[15] += p * v3.w;
        }
    }

    float invl = 1.f / l;
    float* obase = ctx + ((long)(b * SS + q0 + r)) * DD + h * DKK + quad * 16;
    #pragma unroll
    for (int d = 0; d < 16; d += 4) {
        float4 o;
        o.x = acc[d + 0] * invl; o.y = acc[d + 1] * invl;
        o.z = acc[d + 2] * invl; o.w = acc[d + 3] * invl;
        *(float4*)(obase + d) = o;
    }
}

// ---------------- launch ----------------
extern "C" void kernel_launch(void* const* d_in, const int* in_sizes, int n_in,
                              void* d_out, int out_size)
{
    const float* x    = (const float*)d_in[0];
    const int*   mask = (const int*)  d_in[1];
    const float* wq = (const float*)d_in[2];  const float* bq = (const float*)d_in[3];
    const float* wk = (const float*)d_in[4];  const float* bk = (const float*)d_in[5];
    const float* wv = (const float*)d_in[6];  const float* bv = (const float*)d_in[7];
    const float* wo = (const float*)d_in[8];  const float* bo = (const float*)d_in[9];
    const float* w1 = (const float*)d_in[10]; const float* b1 = (const float*)d_in[11];
    const float* w2 = (const float*)d_in[12]; const float* b2 = (const float*)d_in[13];
    const float* a1 = (const float*)d_in[14]; const float* be1 = (const float*)d_in[15];
    const float* a2 = (const float*)d_in[16]; const float* be2 = (const float*)d_in[17];
    float* out = (float*)d_out;

    float *xn, *q, *k, *v, *ctx, *x1, *xn2, *ffh;
    cudaGetSymbolAddress((void**)&xn,  g_xn);
    cudaGetSymbolAddress((void**)&q,   g_q);
    cudaGetSymbolAddress((void**)&k,   g_k);
    cudaGetSymbolAddress((void**)&v,   g_v);
    cudaGetSymbolAddress((void**)&ctx, g_ctx);
    cudaGetSymbolAddress((void**)&x1,  g_x1);
    cudaGetSymbolAddress((void**)&xn2, g_xn2);
    cudaGetSymbolAddress((void**)&ffh, g_ffh);

    dim3 gD (DD   / 128, MR / 128);   // (8, 32)
    dim3 gFF(DFFV / 128, MR / 128);   // (32, 32)

    // LN1
    layernorm_kernel<<<MR, 256>>>(x, xn, a1, be1);
    // Q, K, V projections
    sgemm_kernel<true,  false, false><<<gD, 256>>>(xn, wq, bq, nullptr, q, DD, DD);
    sgemm_kernel<true,  false, false><<<gD, 256>>>(xn, wk, bk, nullptr, k, DD, DD);
    sgemm_kernel<true,  false, false><<<gD, 256>>>(xn, wv, bv, nullptr, v, DD, DD);
    // attention
    attention_kernel<<<dim3(SS / 64, BB * HH), 256>>>(q, k, v, mask, ctx);
    // O projection + residual 1
    sgemm_kernel<true,  false, true ><<<gD, 256>>>(ctx, wo, bo, x, x1, DD, DD);
    // LN2
    layernorm_kernel<<<MR, 256>>>(x1, xn2, a2, be2);
    // FFN
    sgemm_kernel<true,  true,  false><<<gFF, 256>>>(xn2, w1, b1, nullptr, ffh, DD, DFFV);
    sgemm_kernel<true,  false, true ><<<gD, 256>>>(ffh, w2, b2, x1, out, DFFV, DD);
}

// round 3
// speedup vs baseline: 2.7323x; 2.7315x over previous
#include <cuda_runtime.h>
#include <math.h>

#define BB 4
#define SS 1024
#define DD 1024
#define HH 16
#define DKK 64
#define DFFV 4096
#define MR (BB*SS)
#define LN_EPS 1e-6f

__device__ float g_xn [MR*DD];
__device__ float g_q  [MR*DD];
__device__ float g_k  [MR*DD];
__device__ float g_v  [MR*DD];
__device__ float g_ctx[MR*DD];
__device__ float g_x1 [MR*DD];
__device__ float g_xn2[MR*DD];
__device__ float g_ffh[MR*DFFV];
__device__ float g_wq [DD*DD];
__device__ float g_wk [DD*DD];
__device__ float g_wv [DD*DD];
__device__ float g_wo [DD*DD];
__device__ float g_w1 [DD*DFFV];
__device__ float g_w2 [DFFV*DD];

__device__ __forceinline__ float tf32r(float x) {
    unsigned u;
    asm("cvt.rna.tf32.f32 %0, %1;" : "=r"(u) : "f"(x));
    return __uint_as_float(u);
}

__device__ __forceinline__ void mma_tf32(float* c, const unsigned* a, unsigned b0, unsigned b1) {
    asm volatile(
        "mma.sync.aligned.m16n8k8.row.col.f32.tf32.tf32.f32 "
        "{%0,%1,%2,%3}, {%4,%5,%6,%7}, {%8,%9}, {%0,%1,%2,%3};\n"
        : "+f"(c[0]), "+f"(c[1]), "+f"(c[2]), "+f"(c[3])
        : "r"(a[0]), "r"(a[1]), "r"(a[2]), "r"(a[3]), "r"(b0), "r"(b1));
}

__global__ __launch_bounds__(256)
void tf32_round_kernel(const float* __restrict__ in, float* __restrict__ out, int n4)
{
    int i = blockIdx.x * 256 + threadIdx.x;
    if (i < n4) {
        float4 v = ((const float4*)in)[i];
        v.x = tf32r(v.x); v.y = tf32r(v.y); v.z = tf32r(v.z); v.w = tf32r(v.w);
        ((float4*)out)[i] = v;
    }
}

// LayerNorm: torch ddof=1, eps on std; output tf32-rounded (feeds mma GEMMs)
__global__ __launch_bounds__(256)
void layernorm_kernel(const float* __restrict__ x, float* __restrict__ out,
                      const float* __restrict__ alpha, const float* __restrict__ beta)
{
    int row = blockIdx.x;
    float4 v = ((const float4*)(x + (long)row * DD))[threadIdx.x];
    float s  = v.x + v.y + v.z + v.w;
    float sq = v.x*v.x + v.y*v.y + v.z*v.z + v.w*v.w;
    #pragma unroll
    for (int o = 16; o; o >>= 1) {
        s  += __shfl_down_sync(0xffffffffu, s,  o);
        sq += __shfl_down_sync(0xffffffffu, sq, o);
    }
    __shared__ float red[16];
    __shared__ float stats[2];
    int warp = threadIdx.x >> 5, lane = threadIdx.x & 31;
    if (lane == 0) { red[warp] = s; red[warp + 8] = sq; }
    __syncthreads();
    if (threadIdx.x == 0) {
        float ts = 0.f, tq = 0.f;
        #pragma unroll
        for (int i = 0; i < 8; i++) { ts += red[i]; tq += red[i + 8]; }
        float mean = ts / (float)DD;
        float var  = (tq - (float)DD * mean * mean) / (float)(DD - 1);
        var = fmaxf(var, 0.f);
        stats[0] = mean; stats[1] = 1.f / (sqrtf(var) + LN_EPS);
    }
    __syncthreads();
    float mean = stats[0], rstd = stats[1];
    float a = alpha[0], b = beta[0];
    float4 o;
    o.x = tf32r(a * (v.x - mean) * rstd + b);
    o.y = tf32r(a * (v.y - mean) * rstd + b);
    o.z = tf32r(a * (v.z - mean) * rstd + b);
    o.w = tf32r(a * (v.w - mean) * rstd + b);
    ((float4*)(out + (long)row * DD))[threadIdx.x] = o;
}

// tf32 tensor-core GEMM: 128x128 tile, BK=16, 8 warps (2x4), warp 64x32
#define AST 20
#define BST 132

template<bool BIAS, bool RELU, bool RES, bool CVT>
__global__ __launch_bounds__(256)
void mma_gemm(const float* __restrict__ A, const float* __restrict__ Bm,
              const float* __restrict__ bias, const float* __restrict__ res,
              float* __restrict__ C, int K, int N)
{
    __shared__ float As[2][128 * AST];
    __shared__ float Bs[2][16 * BST];

    int tid = threadIdx.x;
    int rowBase = blockIdx.y << 7, colBase = blockIdx.x << 7;
    const float* Ag = A + (long)rowBase * K;
    const float* Bg = Bm + colBase;

    int a_r = tid >> 2, a_c = (tid & 3) << 2;
    int b_k = tid >> 5, b_c = (tid & 31) << 2;
    int warp = tid >> 5, lane = tid & 31;
    int lq = lane >> 2, lr = lane & 3;
    int wm = warp >> 2, wn = warp & 3;

    float acc[4][4][4];
    #pragma unroll
    for (int i = 0; i < 4; i++)
        #pragma unroll
        for (int j = 0; j < 4; j++)
            #pragma unroll
            for (int v = 0; v < 4; v++) acc[i][j][v] = 0.f;

    int T = K >> 4;
    float4 va0 = *(const float4*)(Ag + a_r * K + a_c);
    float4 va1 = *(const float4*)(Ag + (a_r + 64) * K + a_c);
    float4 vb0 = *(const float4*)(Bg + (long)b_k * N + b_c);
    float4 vb1 = *(const float4*)(Bg + (long)(b_k + 8) * N + b_c);
    *(float4*)&As[0][a_r * AST + a_c]        = va0;
    *(float4*)&As[0][(a_r + 64) * AST + a_c] = va1;
    *(float4*)&Bs[0][b_k * BST + b_c]        = vb0;
    *(float4*)&Bs[0][(b_k + 8) * BST + b_c]  = vb1;

    for (int t = 0; t < T; t++) {
        __syncthreads();
        int buf = t & 1;
        if (t + 1 < T) {
            int k0 = (t + 1) << 4;
            va0 = *(const float4*)(Ag + a_r * K + k0 + a_c);
            va1 = *(const float4*)(Ag + (a_r + 64) * K + k0 + a_c);
            vb0 = *(const float4*)(Bg + (long)(k0 + b_k) * N + b_c);
            vb1 = *(const float4*)(Bg + (long)(k0 + b_k + 8) * N + b_c);
        }
        const float* Ab = As[buf];
        const float* Bb = Bs[buf];

        unsigned a[4][2][4], b[4][2][2];
        #pragma unroll
        for (int mt = 0; mt < 4; mt++) {
            int r0 = (wm * 64 + mt * 16 + lq) * AST + lr;
            #pragma unroll
            for (int ks = 0; ks < 2; ks++) {
                a[mt][ks][0] = *(const unsigned*)&Ab[r0 + ks * 8];
                a[mt][ks][1] = *(const unsigned*)&Ab[r0 + 8 * AST + ks * 8];
                a[mt][ks][2] = *(const unsigned*)&Ab[r0 + ks * 8 + 4];
                a[mt][ks][3] = *(const unsigned*)&Ab[r0 + 8 * AST + ks * 8 + 4];
            }
        }
        #pragma unroll
        for (int nt = 0; nt < 4; nt++) {
            int c0 = wn * 32 + nt * 8 + lq;
            #pragma unroll
            for (int ks = 0; ks < 2; ks++) {
                b[nt][ks][0] = *(const unsigned*)&Bb[(ks * 8 + lr) * BST + c0];
                b[nt][ks][1] = *(const unsigned*)&Bb[(ks * 8 + lr + 4) * BST + c0];
            }
        }
        #pragma unroll
        for (int ks = 0; ks < 2; ks++)
            #pragma unroll
            for (int mt = 0; mt < 4; mt++)
                #pragma unroll
                for (int nt = 0; nt < 4; nt++)
                    mma_tf32(acc[mt][nt], a[mt][ks], b[nt][ks][0], b[nt][ks][1]);

        if (t + 1 < T) {
            *(float4*)&As[buf ^ 1][a_r * AST + a_c]        = va0;
            *(float4*)&As[buf ^ 1][(a_r + 64) * AST + a_c] = va1;
            *(float4*)&Bs[buf ^ 1][b_k * BST + b_c]        = vb0;
            *(float4*)&Bs[buf ^ 1][(b_k + 8) * BST + b_c]  = vb1;
        }
    }

    int erow = rowBase + wm * 64 + lq;
    int ecol = colBase + wn * 32 + lr * 2;
    #pragma unroll
    for (int mt = 0; mt < 4; mt++) {
        #pragma unroll
        for (int nt = 0; nt < 4; nt++) {
            int r = erow + mt * 16;
            int c = ecol + nt * 8;
            float lo0 = acc[mt][nt][0], lo1 = acc[mt][nt][1];
            float hi0 = acc[mt][nt][2], hi1 = acc[mt][nt][3];
            if (BIAS) {
                float2 bv = *(const float2*)(bias + c);
                lo0 += bv.x; lo1 += bv.y; hi0 += bv.x; hi1 += bv.y;
            }
            if (RELU) {
                lo0 = fmaxf(lo0, 0.f); lo1 = fmaxf(lo1, 0.f);
                hi0 = fmaxf(hi0, 0.f); hi1 = fmaxf(hi1, 0.f);
            }
            if (RES) {
                float2 r0 = *(const float2*)(res + (long)r * N + c);
                float2 r1 = *(const float2*)(res + (long)(r + 8) * N + c);
                lo0 += r0.x; lo1 += r0.y; hi0 += r1.x; hi1 += r1.y;
            }
            if (CVT) {
                lo0 = tf32r(lo0); lo1 = tf32r(lo1);
                hi0 = tf32r(hi0); hi1 = tf32r(hi1);
            }
            float2 wlo = {lo0, lo1}, whi = {hi0, hi1};
            *(float2*)(C + (long)r * N + c)       = wlo;
            *(float2*)(C + (long)(r + 8) * N + c) = whi;
        }
    }
}

// flash attention: 128 q rows x 64 k per tile, 4x8 microtile, shuffle-PV
#define ATT_SMEM_BYTES ((64*128 + 64*64 + 64*64) * 4 + 64 * 4)

__global__ __launch_bounds__(256)
void attention_kernel(const float* __restrict__ q, const float* __restrict__ k,
                      const float* __restrict__ v, const int* __restrict__ mask,
                      float* __restrict__ ctx)
{
    extern __shared__ float sm[];
    float* Qt = sm;              // [d=64][row=128]
    float* Kt = sm + 64 * 128;   // [d=64][kpos=64]
    float* Vs = Kt + 64 * 64;    // [kpos=64][d=64]
    int*   msk = (int*)(Vs + 64 * 64);

    int bh = blockIdx.y;
    int b = bh >> 4, h = bh & 15;
    int q0 = blockIdx.x * 128;
    int tid = threadIdx.x;
    int ty = tid >> 3;   // 0..31 -> q rows ty*4+{0..3}
    int tx = tid & 7;    // 0..7  -> 8-wide col/dim slice

    const float* qg = q + ((long)(b * SS + q0)) * DD + h * DKK;
    const float* kg = k + ((long)b * SS) * DD + h * DKK;
    const float* vg = v + ((long)b * SS) * DD + h * DKK;
    const int* mrow = mask + b * SS;

    #pragma unroll
    for (int i = 0; i < 8; i++) {
        int fi = tid + i * 256;
        int row = fi & 127;
        int c4 = (fi >> 7) << 2;
        float4 t = *(const float4*)(qg + (long)row * DD + c4);
        Qt[(c4 + 0) * 128 + row] = t.x; Qt[(c4 + 1) * 128 + row] = t.y;
        Qt[(c4 + 2) * 128 + row] = t.z; Qt[(c4 + 3) * 128 + row] = t.w;
    }

    float m_[4], l_[4], acc[4][8];
    #pragma unroll
    for (int i = 0; i < 4; i++) {
        m_[i] = -INFINITY; l_[i] = 0.f;
        #pragma unroll
        for (int j = 0; j < 8; j++) acc[i][j] = 0.f;
    }

    for (int kt = 0; kt < 16; kt++) {
        int k0 = kt * 64;
        __syncthreads();
        #pragma unroll
        for (int i = 0; i < 4; i++) {
            int fi = tid + i * 256;
            int kr = fi & 63;
            int c4 = (fi >> 6) << 2;
            float4 t = *(const float4*)(kg + (long)(k0 + kr) * DD + c4);
            Kt[(c4 + 0) * 64 + kr] = t.x; Kt[(c4 + 1) * 64 + kr] = t.y;
            Kt[(c4 + 2) * 64 + kr] = t.z; Kt[(c4 + 3) * 64 + kr] = t.w;
            int kr2 = fi >> 4;
            int d4 = (fi & 15) << 2;
            *(float4*)(Vs + kr2 * 64 + d4) = *(const float4*)(vg + (long)(k0 + kr2) * DD + d4);
        }
        if (tid < 16) ((int4*)msk)[tid] = ((const int4*)(mrow + k0))[tid];
        __syncthreads();

        float s[4][8];
        #pragma unroll
        for (int i = 0; i < 4; i++)
            #pragma unroll
            for (int j = 0; j < 8; j++) s[i][j] = 0.f;

        #pragma unroll 8
        for (int kk = 0; kk < 64; kk++) {
            float4 a = *(const float4*)(Qt + kk * 128 + ty * 4);
            float4 b0 = *(const float4*)(Kt + kk * 64 + tx * 8);
            float4 b1 = *(const float4*)(Kt + kk * 64 + tx * 8 + 4);
            float av[4] = {a.x, a.y, a.z, a.w};
            float bv[8] = {b0.x, b0.y, b0.z, b0.w, b1.x, b1.y, b1.z, b1.w};
            #pragma unroll
            for (int i = 0; i < 4; i++)
                #pragma unroll
                for (int j = 0; j < 8; j++)
                    s[i][j] += av[i] * bv[j];
        }

        int mloc[8];
        #pragma unroll
        for (int j = 0; j < 8; j++) mloc[j] = msk[tx * 8 + j];

        #pragma unroll
        for (int i = 0; i < 4; i++) {
            float rmax = -INFINITY;
            #pragma unroll
            for (int j = 0; j < 8; j++) {
                float sv = s[i][j] * 0.125f;
                if (mloc[j] == 0) sv = -1e9f;
                s[i][j] = sv;
                rmax = fmaxf(rmax, sv);
            }
            // xor 1/2/4 stays within the 8-lane tx group
            rmax = fmaxf(rmax, __shfl_xor_sync(0xffffffffu, rmax, 1));
            rmax = fmaxf(rmax, __shfl_xor_sync(0xffffffffu, rmax, 2));
            rmax = fmaxf(rmax, __shfl_xor_sync(0xffffffffu, rmax, 4));
            float mn = fmaxf(m_[i], rmax);
            float corr = __expf(m_[i] - mn);
            float ps = 0.f;
            #pragma unroll
            for (int j = 0; j < 8; j++) {
                float p = __expf(s[i][j] - mn);
                s[i][j] = p;
                ps += p;
            }
            ps += __shfl_xor_sync(0xffffffffu, ps, 1);
            ps += __shfl_xor_sync(0xffffffffu, ps, 2);
            ps += __shfl_xor_sync(0xffffffffu, ps, 4);
            l_[i] = l_[i] * corr + ps;
            m_[i] = mn;
            #pragma unroll
            for (int j = 0; j < 8; j++) acc[i][j] *= corr;
        }

        // acc += P @ V via width-8 shuffles
        #pragma unroll
        for (int src = 0; src < 8; src++) {
            #pragma unroll
            for (int j = 0; j < 8; j++) {
                int kp = src * 8 + j;
                float p0 = __shfl_sync(0xffffffffu, s[0][j], src, 8);
                float p1 = __shfl_sync(0xffffffffu, s[1][j], src, 8);
                float p2 = __shfl_sync(0xffffffffu, s[2][j], src, 8);
                float p3 = __shfl_sync(0xffffffffu, s[3][j], src, 8);
                float4 v0 = *(const float4*)(Vs + kp * 64 + tx * 8);
                float4 v1 = *(const float4*)(Vs + kp * 64 + tx * 8 + 4);
                float vv[8] = {v0.x, v0.y, v0.z, v0.w, v1.x, v1.y, v1.z, v1.w};
                #pragma unroll
                for (int d = 0; d < 8; d++) {
                    acc[0][d] += p0 * vv[d];
                    acc[1][d] += p1 * vv[d];
                    acc[2][d] += p2 * vv[d];
                    acc[3][d] += p3 * vv[d];
                }
            }
        }
    }

    #pragma unroll
    for (int i = 0; i < 4; i++) {
        int row = q0 + ty * 4 + i;
        float inv = 1.f / l_[i];
        float* ob = ctx + ((long)(b * SS + row)) * DD + h * DKK + tx * 8;
        float4 o0, o1;
        o0.x = tf32r(acc[i][0] * inv); o0.y = tf32r(acc[i][1] * inv);
        o0.z = tf32r(acc[i][2] * inv); o0.w = tf32r(acc[i][3] * inv);
        o1.x = tf32r(acc[i][4] * inv); o1.y = tf32r(acc[i][5] * inv);
        o1.z = tf32r(acc[i][6] * inv); o1.w = tf32r(acc[i][7] * inv);
        *(float4*)ob = o0;
        *(float4*)(ob + 4) = o1;
    }
}

extern "C" void kernel_launch(void* const* d_in, const int* in_sizes, int n_in,
                              void* d_out, int out_size)
{
    const float* x    = (const float*)d_in[0];
    const int*   mask = (const int*)  d_in[1];
    const float* wq = (const float*)d_in[2];  const float* bq = (const float*)d_in[3];
    const float* wk = (const float*)d_in[4];  const float* bk = (const float*)d_in[5];
    const float* wv = (const float*)d_in[6];  const float* bv = (const float*)d_in[7];
    const float* wo = (const float*)d_in[8];  const float* bo = (const float*)d_in[9];
    const float* w1 = (const float*)d_in[10]; const float* b1 = (const float*)d_in[11];
    const float* w2 = (const float*)d_in[12]; const float* b2 = (const float*)d_in[13];
    const float* a1 = (const float*)d_in[14]; const float* be1 = (const float*)d_in[15];
    const float* a2 = (const float*)d_in[16]; const float* be2 = (const float*)d_in[17];
    float* out = (float*)d_out;

    float *xn, *q, *k, *v, *ctx, *x1, *xn2, *ffh;
    float *wqr, *wkr, *wvr, *wor, *w1r, *w2r;
    cudaGetSymbolAddress((void**)&xn,  g_xn);
    cudaGetSymbolAddress((void**)&q,   g_q);
    cudaGetSymbolAddress((void**)&k,   g_k);
    cudaGetSymbolAddress((void**)&v,   g_v);
    cudaGetSymbolAddress((void**)&ctx, g_ctx);
    cudaGetSymbolAddress((void**)&x1,  g_x1);
    cudaGetSymbolAddress((void**)&xn2, g_xn2);
    cudaGetSymbolAddress((void**)&ffh, g_ffh);
    cudaGetSymbolAddress((void**)&wqr, g_wq);
    cudaGetSymbolAddress((void**)&wkr, g_wk);
    cudaGetSymbolAddress((void**)&wvr, g_wv);
    cudaGetSymbolAddress((void**)&wor, g_wo);
    cudaGetSymbolAddress((void**)&w1r, g_w1);
    cudaGetSymbolAddress((void**)&w2r, g_w2);

    static int att_attr_set = 0;
    if (!att_attr_set) {
        cudaFuncSetAttribute(attention_kernel,
                             cudaFuncAttributeMaxDynamicSharedMemorySize, ATT_SMEM_BYTES);
        att_attr_set = 1;
    }

    int nDD4  = DD * DD / 4;
    int nDF4  = DD * DFFV / 4;
    tf32_round_kernel<<<nDD4 / 256, 256>>>(wq, wqr, nDD4);
    tf32_round_kernel<<<nDD4 / 256, 256>>>(wk, wkr, nDD4);
    tf32_round_kernel<<<nDD4 / 256, 256>>>(wv, wvr, nDD4);
    tf32_round_kernel<<<nDD4 / 256, 256>>>(wo, wor, nDD4);
    tf32_round_kernel<<<nDF4 / 256, 256>>>(w1, w1r, nDF4);
    tf32_round_kernel<<<nDF4 / 256, 256>>>(w2, w2r, nDF4);

    dim3 gD (DD   / 128, MR / 128);
    dim3 gFF(DFFV / 128, MR / 128);

    layernorm_kernel<<<MR, 256>>>(x, xn, a1, be1);
    mma_gemm<true,  false, false, false><<<gD, 256>>>(xn, wqr, bq, nullptr, q, DD, DD);
    mma_gemm<true,  false, false, false><<<gD, 256>>>(xn, wkr, bk, nullptr, k, DD, DD);
    mma_gemm<true,  false, false, false><<<gD, 256>>>(xn, wvr, bv, nullptr, v, DD, DD);
    attention_kernel<<<dim3(SS / 128, BB * HH), 256, ATT_SMEM_BYTES>>>(q, k, v, mask, ctx);
    mma_gemm<true,  false, true,  false><<<gD, 256>>>(ctx, wor, bo, x, x1, DD, DD);
    layernorm_kernel<<<MR, 256>>>(x1, xn2, a2, be2);
    mma_gemm<true,  true,  false, true ><<<gFF, 256>>>(xn2, w1r, b1, nullptr, ffh, DD, DFFV);
    mma_gemm<true,  false, true,  false><<<gD, 256>>>(ffh, w2r, b2, x1, out, DFFV, DD);
}